// round 8
// baseline (speedup 1.0000x reference)
#include <cuda_runtime.h>
#include <cuda_bf16.h>
#include <cstdint>

// ---------------------------------------------------------------------------
// Problem constants
// ---------------------------------------------------------------------------
#define BATCH     256
#define D_MODEL   2048
#define D_STATE   128
#define D_CONV    4
#define D_SSM     4096
#define NHEADS    64
#define HEADDIM   64
#define CONV_DIM  (D_SSM + 2 * D_STATE)              // 4352
#define D_IN_PROJ (2 * D_SSM + 2 * D_STATE + NHEADS) // 8512

#define OUT_N   (BATCH * D_MODEL)
#define CONV_N  (BATCH * CONV_DIM * D_CONV)
#define SSM_OFF (OUT_N + CONV_N)

// in_proj N-chunk boundary (in tiles of 64): 67 tiles = 4288 columns
#define IPN0_TILES 67
#define IPN0_COLS  (IPN0_TILES * 64)                 // 4288
#define IPN1_TILES (D_IN_PROJ / 64 - IPN0_TILES)     // 66

// ---------------------------------------------------------------------------
// Scratch (__device__ globals — no allocation allowed)
// ---------------------------------------------------------------------------
__device__ float g_zxbcdt[(size_t)BATCH * D_IN_PROJ];
__device__ float g_act[(size_t)BATCH * CONV_DIM];

__device__ __nv_bfloat16 g_ip_hi[(size_t)D_IN_PROJ * D_MODEL];
__device__ __nv_bfloat16 g_ip_lo[(size_t)D_IN_PROJ * D_MODEL];
__device__ __nv_bfloat16 g_op_hi[(size_t)D_MODEL * D_SSM];
__device__ __nv_bfloat16 g_op_lo[(size_t)D_MODEL * D_SSM];
__device__ __nv_bfloat16 g_h_hi[(size_t)BATCH * D_MODEL];
__device__ __nv_bfloat16 g_h_lo[(size_t)BATCH * D_MODEL];
__device__ __nv_bfloat16 g_yz_hi[(size_t)BATCH * D_SSM];
__device__ __nv_bfloat16 g_yz_lo[(size_t)BATCH * D_SSM];

// ---------------------------------------------------------------------------
// PTX helpers
// ---------------------------------------------------------------------------
__device__ __forceinline__ void ldsm4(uint32_t* r, uint32_t addr) {
    asm volatile("ldmatrix.sync.aligned.m8n8.x4.shared.b16 {%0,%1,%2,%3}, [%4];"
                 : "=r"(r[0]), "=r"(r[1]), "=r"(r[2]), "=r"(r[3]) : "r"(addr));
}

__device__ __forceinline__ void mma_bf16(float* d, const uint32_t* a,
                                         const uint32_t* b) {
    asm volatile(
        "mma.sync.aligned.m16n8k16.row.col.f32.bf16.bf16.f32 "
        "{%0,%1,%2,%3}, {%4,%5,%6,%7}, {%8,%9}, {%0,%1,%2,%3};"
        : "+f"(d[0]), "+f"(d[1]), "+f"(d[2]), "+f"(d[3])
        : "r"(a[0]), "r"(a[1]), "r"(a[2]), "r"(a[3]), "r"(b[0]), "r"(b[1]));
}

__device__ __forceinline__ uint32_t smem_u32(const void* p) {
    uint32_t a;
    asm("{ .reg .u64 t; cvta.to.shared.u64 t, %1; cvt.u32.u64 %0, t; }"
        : "=r"(a) : "l"(p));
    return a;
}

__device__ __forceinline__ void cpasync16(uint32_t dst, const void* src) {
    asm volatile("cp.async.cg.shared.global [%0], [%1], 16;"
                 :: "r"(dst), "l"(src));
}
#define CP_COMMIT() asm volatile("cp.async.commit_group;" ::: "memory")
#define CP_WAIT(n)  asm volatile("cp.async.wait_group %0;" :: "n"(n) : "memory")

#define SW128(bo) ((bo) ^ (((bo) >> 3) & 0x70))

__device__ __forceinline__ void split4(const float4& v, uint2& hi, uint2& lo) {
    float f[4] = {v.x, v.y, v.z, v.w};
    uint32_t h[2], l[2];
#pragma unroll
    for (int i = 0; i < 2; i++) {
        uint32_t w;
        asm("cvt.rn.bf16x2.f32 %0, %1, %2;" : "=r"(w) : "f"(f[2*i+1]), "f"(f[2*i]));
        float h0 = __uint_as_float(w << 16);
        float h1 = __uint_as_float(w & 0xffff0000u);
        float l0 = f[2*i]   - h0;
        float l1 = f[2*i+1] - h1;
        uint32_t wl;
        asm("cvt.rn.bf16x2.f32 %0, %1, %2;" : "=r"(wl) : "f"(l1), "f"(l0));
        h[i] = w; l[i] = wl;
    }
    hi = make_uint2(h[0], h[1]);
    lo = make_uint2(l[0], l[1]);
}

__global__ __launch_bounds__(256) void split_kernel(
    const float4* __restrict__ in, uint2* __restrict__ hi,
    uint2* __restrict__ lo, int n4)
{
    int i = blockIdx.x * 256 + threadIdx.x;
    if (i >= n4) return;
    uint2 h, l;
    split4(in[i], h, l);
    hi[i] = h;
    lo[i] = l;
}

// ---------------------------------------------------------------------------
// bf16 tensor-core GEMM (3-term split), cp.async 2-stage pipeline.
// C[M,N] = A[M,K] @ B[N,K]^T; A,B pre-split bf16 hi/lo (K-major).
// Block tile 128x64, BK=64. 256 thr, 8 warps (4x2), 32x32 per warp.
// Stage 48 KB; 2 stages = 96 KB dynamic smem.   (round-6 measured config)
// ---------------------------------------------------------------------------
#define BKC 64
#define STG 49152
#define ST_AHI 0
#define ST_ALO 16384
#define ST_BHI 32768
#define ST_BLO 40960
#define GEMM_SMEM (2 * STG)

template <bool ATOMIC>
__global__ __launch_bounds__(256) void gemm_bf16_tc(
    const __nv_bfloat16* __restrict__ Ahi, const __nv_bfloat16* __restrict__ Alo,
    const __nv_bfloat16* __restrict__ Bhi, const __nv_bfloat16* __restrict__ Blo,
    float* __restrict__ C, int M, int N, int K, int klen)
{
    extern __shared__ __align__(1024) char sm[];
    const uint32_t sb = smem_u32(sm);

    const int tid  = threadIdx.x;
    const int lane = tid & 31;
    const int warp = tid >> 5;
    const int n0 = blockIdx.x * 64;
    const int m0 = blockIdx.y * 128;
    const int k0 = blockIdx.z * klen;
    const int wm = warp >> 1;
    const int wn = warp & 1;

    uint32_t a_sw[4], b_sw[2];
    const __nv_bfloat16 *a_src[4], *b_src[2];
#pragma unroll
    for (int t = 0; t < 4; t++) {
        int idx = tid + t * 256;
        int r = idx >> 3, g = idx & 7;
        a_sw[t] = SW128((uint32_t)(r * 128 + g * 16));
        a_src[t] = Ahi + (size_t)(m0 + r) * K + k0 + g * 8;
    }
#pragma unroll
    for (int t = 0; t < 2; t++) {
        int idx = tid + t * 256;
        int r = idx >> 3, g = idx & 7;
        b_sw[t] = SW128((uint32_t)(r * 128 + g * 16));
        b_src[t] = Bhi + (size_t)(n0 + r) * K + k0 + g * 8;
    }
    const ptrdiff_t dAL = Alo - Ahi;
    const ptrdiff_t dBL = Blo - Bhi;

    const int g4 = lane >> 3;
    const int ra = wm * 32 + ((g4 & 1) << 3) + (lane & 7);
    const uint32_t a_xm   = (uint32_t)(ra & 7) << 4;
    const uint32_t a_row  = (uint32_t)(ra * 128);
    const uint32_t a_koff = (uint32_t)(g4 >> 1) << 4;

    const int rb = wn * 32 + ((g4 >> 1) << 3) + (lane & 7);
    const uint32_t b_xm   = (uint32_t)(rb & 7) << 4;
    const uint32_t b_row  = (uint32_t)(rb * 128);
    const uint32_t b_koff = (uint32_t)(g4 & 1) << 4;

    float acc[2][4][4];
#pragma unroll
    for (int i = 0; i < 2; i++)
#pragma unroll
        for (int j = 0; j < 4; j++)
#pragma unroll
            for (int v = 0; v < 4; v++) acc[i][j][v] = 0.0f;

    const int nch = klen / BKC;

    {
        const uint32_t s0 = sb;
#pragma unroll
        for (int t = 0; t < 4; t++) {
            cpasync16(s0 + ST_AHI + a_sw[t], a_src[t]);
            cpasync16(s0 + ST_ALO + a_sw[t], a_src[t] + dAL);
        }
#pragma unroll
        for (int t = 0; t < 2; t++) {
            cpasync16(s0 + ST_BHI + b_sw[t], b_src[t]);
            cpasync16(s0 + ST_BLO + b_sw[t], b_src[t] + dBL);
        }
        CP_COMMIT();
    }

    for (int c = 0; c < nch; c++) {
        if (c + 1 < nch) {
            const uint32_t sn = sb + ((c + 1) & 1) * STG;
            const int koff = (c + 1) * BKC;
#pragma unroll
            for (int t = 0; t < 4; t++) {
                cpasync16(sn + ST_AHI + a_sw[t], a_src[t] + koff);
                cpasync16(sn + ST_ALO + a_sw[t], a_src[t] + koff + dAL);
            }
#pragma unroll
            for (int t = 0; t < 2; t++) {
                cpasync16(sn + ST_BHI + b_sw[t], b_src[t] + koff);
                cpasync16(sn + ST_BLO + b_sw[t], b_src[t] + koff + dBL);
            }
            CP_COMMIT();
            CP_WAIT(1);
        } else {
            CP_WAIT(0);
        }
        __syncthreads();

        const uint32_t ss = sb + (c & 1) * STG;
        const uint32_t a_base = ss + ST_AHI + a_row;
        const uint32_t b_base = ss + ST_BHI + b_row;

#pragma unroll
        for (int ks = 0; ks < 4; ks++) {
            uint32_t ah[2][4], al[2][4], bh[2][4], bl[2][4];
            const uint32_t ak = ((uint32_t)(32 * ks) | a_koff) ^ a_xm;
            const uint32_t bk = ((uint32_t)(32 * ks) | b_koff) ^ b_xm;
#pragma unroll
            for (int i = 0; i < 2; i++) {
                uint32_t ad = a_base + i * 2048 + ak;
                ldsm4(ah[i], ad);
                ldsm4(al[i], ad + (ST_ALO - ST_AHI));
            }
#pragma unroll
            for (int jj = 0; jj < 2; jj++) {
                uint32_t bd = b_base + jj * 2048 + bk;
                ldsm4(bh[jj], bd);
                ldsm4(bl[jj], bd + (ST_BLO - ST_BHI));
            }
#pragma unroll
            for (int i = 0; i < 2; i++) {
#pragma unroll
                for (int j = 0; j < 4; j++) {
                    const uint32_t* Bh = &bh[j >> 1][(j & 1) * 2];
                    const uint32_t* Bl = &bl[j >> 1][(j & 1) * 2];
                    mma_bf16(acc[i][j], ah[i], Bh);
                    mma_bf16(acc[i][j], al[i], Bh);
                    mma_bf16(acc[i][j], ah[i], Bl);
                }
            }
        }
        __syncthreads();
    }

#pragma unroll
    for (int i = 0; i < 2; i++) {
#pragma unroll
        for (int j = 0; j < 4; j++) {
            int row = m0 + wm * 32 + i * 16 + (lane >> 2);
            int col = n0 + wn * 32 + j * 8 + (lane & 3) * 2;
            size_t o0 = (size_t)row * N + col;
            size_t o1 = (size_t)(row + 8) * N + col;
            if (ATOMIC) {
                atomicAdd(&C[o0],     acc[i][j][0]);
                atomicAdd(&C[o0 + 1], acc[i][j][1]);
                atomicAdd(&C[o1],     acc[i][j][2]);
                atomicAdd(&C[o1 + 1], acc[i][j][3]);
            } else {
                *(float2*)(C + o0) = make_float2(acc[i][j][0], acc[i][j][1]);
                *(float2*)(C + o1) = make_float2(acc[i][j][2], acc[i][j][3]);
            }
        }
    }
}

// ---------------------------------------------------------------------------
// Conv step
// ---------------------------------------------------------------------------
__global__ __launch_bounds__(256) void conv_kernel(
    const float* __restrict__ conv_in,
    const float* __restrict__ conv_w,
    const float* __restrict__ conv_b,
    float* __restrict__ conv_out)
{
    const int c = blockIdx.x * 256 + threadIdx.x;
    const int b = blockIdx.y;
    const size_t idx = (size_t)b * CONV_DIM + c;

    float4 s = *(const float4*)(conv_in + idx * 4);
    float4 w = *(const float4*)(conv_w + (size_t)c * 4);
    float xin = g_zxbcdt[(size_t)b * D_IN_PROJ + D_SSM + c];

    float v = s.y * w.x + s.z * w.y + s.w * w.z + xin * w.w + conv_b[c];
    float act = v / (1.0f + expf(-v));

    *(float4*)(conv_out + idx * 4) = make_float4(s.y, s.z, s.w, xin);
    g_act[idx] = act;
}

// ---------------------------------------------------------------------------
// SSM fused kernel — batch-sliced (b_off) for ssm/out_proj pipelining
// ---------------------------------------------------------------------------
__global__ __launch_bounds__(256) void ssm_kernel(
    const float* __restrict__ ssm_in,
    const float* __restrict__ dt_bias,
    const float* __restrict__ A_log,
    const float* __restrict__ Dvec,
    float* __restrict__ ssm_out,
    int b_off)
{
    const int h = blockIdx.x;
    const int b = blockIdx.y + b_off;
    const int tid = threadIdx.x;

    __shared__ __align__(16) float sB[D_STATE];
    __shared__ __align__(16) float sC[D_STATE];
    __shared__ float s_dt, s_dA, s_Dh;

    if (tid == 0) {
        float v = g_zxbcdt[(size_t)b * D_IN_PROJ + (2 * D_SSM + 2 * D_STATE) + h]
                  + dt_bias[h];
        float dt = fmaxf(v, 0.0f) + log1pf(expf(-fabsf(v)));
        float A  = -expf(A_log[h]);
        s_dt = dt;
        s_dA = expf(dt * A);
        s_Dh = Dvec[h];
    }
    if (tid < D_STATE) {
        sB[tid] = g_act[(size_t)b * CONV_DIM + D_SSM + tid];
        sC[tid] = g_act[(size_t)b * CONV_DIM + D_SSM + D_STATE + tid];
    }
    __syncthreads();

    const float dt = s_dt, dA = s_dA, Dh = s_Dh;
    const int warp = tid >> 5, lane = tid & 31;

    const float* base_in  = ssm_in  + (((size_t)b * NHEADS + h) * HEADDIM) * D_STATE;
    float*       base_out = ssm_out + (((size_t)b * NHEADS + h) * HEADDIM) * D_STATE;

    const float4 bbv = *(const float4*)&sB[lane * 4];
    const float4 ccv = *(const float4*)&sC[lane * 4];

#pragma unroll
    for (int r = 0; r < 8; r++) {
        const int p = warp * 8 + r;
        float x = g_act[(size_t)b * CONV_DIM + h * HEADDIM + p];
        float xdt = x * dt;

        float4 st = *(const float4*)(base_in + (size_t)p * D_STATE + lane * 4);
        float n0 = st.x * dA + bbv.x * xdt;
        float n1 = st.y * dA + bbv.y * xdt;
        float n2 = st.z * dA + bbv.z * xdt;
        float n3 = st.w * dA + bbv.w * xdt;
        *(float4*)(base_out + (size_t)p * D_STATE + lane * 4) =
            make_float4(n0, n1, n2, n3);

        float ysum = n0 * ccv.x + n1 * ccv.y + n2 * ccv.z + n3 * ccv.w;
#pragma unroll
        for (int off = 16; off; off >>= 1)
            ysum += __shfl_xor_sync(0xffffffffu, ysum, off);

        if (lane == 0) {
            float y = ysum + Dh * x;
            float z = g_zxbcdt[(size_t)b * D_IN_PROJ + h * HEADDIM + p];
            float sz = z / (1.0f + expf(-z));
            float yz = y * sz;
            size_t oy = (size_t)b * D_SSM + h * HEADDIM + p;
            __nv_bfloat16 hb = __float2bfloat16(yz);
            float hf = __bfloat162float(hb);
            g_yz_hi[oy] = hb;
            g_yz_lo[oy] = __float2bfloat16(yz - hf);
        }
    }
}

__global__ __launch_bounds__(256) void zero_kernel(float4* __restrict__ p, int n4) {
    int i = blockIdx.x * 256 + threadIdx.x;
    if (i < n4) p[i] = make_float4(0.f, 0.f, 0.f, 0.f);
}

// ---------------------------------------------------------------------------
// Launch — multi-stream fork/join (graph-capture-safe pattern)
// ---------------------------------------------------------------------------
extern "C" void kernel_launch(void* const* d_in, const int* in_sizes, int n_in,
                              void* d_out, int out_size)
{
    const float* hidden    = (const float*)d_in[0];
    const float* conv_in   = (const float*)d_in[1];
    const float* ssm_in    = (const float*)d_in[2];
    const float* in_proj_w = (const float*)d_in[3];
    const float* conv_w    = (const float*)d_in[4];
    const float* conv_b    = (const float*)d_in[5];
    const float* dt_bias   = (const float*)d_in[6];
    const float* A_log     = (const float*)d_in[7];
    const float* Dvec      = (const float*)d_in[8];
    const float* out_w     = (const float*)d_in[9];

    float* out_p  = (float*)d_out;
    float* conv_p = out_p + OUT_N;
    float* ssm_p  = out_p + SSM_OFF;

    float* zx; cudaGetSymbolAddress((void**)&zx, g_zxbcdt);
    __nv_bfloat16 *ip_hi, *ip_lo, *op_hi, *op_lo, *h_hi, *h_lo, *yz_hi, *yz_lo;
    cudaGetSymbolAddress((void**)&ip_hi, g_ip_hi);
    cudaGetSymbolAddress((void**)&ip_lo, g_ip_lo);
    cudaGetSymbolAddress((void**)&op_hi, g_op_hi);
    cudaGetSymbolAddress((void**)&op_lo, g_op_lo);
    cudaGetSymbolAddress((void**)&h_hi, g_h_hi);
    cudaGetSymbolAddress((void**)&h_lo, g_h_lo);
    cudaGetSymbolAddress((void**)&yz_hi, g_yz_hi);
    cudaGetSymbolAddress((void**)&yz_lo, g_yz_lo);

    static cudaStream_t s1 = nullptr, s2 = nullptr;
    static cudaEvent_t evRoot, evW0, evW1, evIP, evB, evS0, evO0;
    static bool init_done = false;
    if (!init_done) {
        cudaFuncSetAttribute(gemm_bf16_tc<false>,
            cudaFuncAttributeMaxDynamicSharedMemorySize, GEMM_SMEM);
        cudaFuncSetAttribute(gemm_bf16_tc<true>,
            cudaFuncAttributeMaxDynamicSharedMemorySize, GEMM_SMEM);
        cudaStreamCreateWithFlags(&s1, cudaStreamNonBlocking);
        cudaStreamCreateWithFlags(&s2, cudaStreamNonBlocking);
        cudaEventCreateWithFlags(&evRoot, cudaEventDisableTiming);
        cudaEventCreateWithFlags(&evW0,   cudaEventDisableTiming);
        cudaEventCreateWithFlags(&evW1,   cudaEventDisableTiming);
        cudaEventCreateWithFlags(&evIP,   cudaEventDisableTiming);
        cudaEventCreateWithFlags(&evB,    cudaEventDisableTiming);
        cudaEventCreateWithFlags(&evS0,   cudaEventDisableTiming);
        cudaEventCreateWithFlags(&evO0,   cudaEventDisableTiming);
        init_done = true;
    }

    // ---- fork root ----
    cudaEventRecord(evRoot, 0);

    // ---- side stream s2: out_w split + output zero (off critical path) ----
    cudaStreamWaitEvent(s2, evRoot, 0);
    {
        int n4 = D_MODEL * D_SSM / 4;
        split_kernel<<<(n4 + 255) / 256, 256, 0, s2>>>(
            (const float4*)out_w, (uint2*)op_hi, (uint2*)op_lo, n4);
    }
    zero_kernel<<<(OUT_N / 4 + 255) / 256, 256, 0, s2>>>(
        (float4*)out_p, OUT_N / 4);
    cudaEventRecord(evB, s2);

    // ---- stream 0: hidden split, then in_proj_w split in two chunks ----
    {
        int n4 = BATCH * D_MODEL / 4;
        split_kernel<<<(n4 + 255) / 256, 256>>>(
            (const float4*)hidden, (uint2*)h_hi, (uint2*)h_lo, n4);
    }
    {
        int n4 = IPN0_COLS * D_MODEL / 4;   // rows [0, 4288)
        split_kernel<<<(n4 + 255) / 256, 256>>>(
            (const float4*)in_proj_w, (uint2*)ip_hi, (uint2*)ip_lo, n4);
    }
    cudaEventRecord(evW0, 0);
    {
        size_t off  = (size_t)IPN0_COLS * D_MODEL;
        int n4 = (D_IN_PROJ - IPN0_COLS) * D_MODEL / 4;
        split_kernel<<<(n4 + 255) / 256, 256>>>(
            (const float4*)(in_proj_w + off),
            (uint2*)(ip_hi + off), (uint2*)(ip_lo + off), n4);
    }
    cudaEventRecord(evW1, 0);

    // ---- stream s1: in_proj GEMM pipelined against the weight split ----
    cudaStreamWaitEvent(s1, evW0, 0);
    {
        dim3 grid(IPN0_TILES, BATCH / 128, 1);        // cols [0, 4288)
        gemm_bf16_tc<false><<<grid, 256, GEMM_SMEM, s1>>>(
            h_hi, h_lo, ip_hi, ip_lo, zx,
            BATCH, D_IN_PROJ, D_MODEL, D_MODEL);
    }
    cudaStreamWaitEvent(s1, evW1, 0);
    {
        size_t woff = (size_t)IPN0_COLS * D_MODEL;
        dim3 grid(IPN1_TILES, BATCH / 128, 1);        // cols [4288, 8512)
        gemm_bf16_tc<false><<<grid, 256, GEMM_SMEM, s1>>>(
            h_hi, h_lo, ip_hi + woff, ip_lo + woff, zx + IPN0_COLS,
            BATCH, D_IN_PROJ, D_MODEL, D_MODEL);
    }
    cudaEventRecord(evIP, s1);

    // ---- stream 0: conv -> ssm half 0 -> ssm half 1 ----
    cudaStreamWaitEvent(0, evIP, 0);
    {
        dim3 grid(CONV_DIM / 256, BATCH, 1);
        conv_kernel<<<grid, 256>>>(conv_in, conv_w, conv_b, conv_p);
    }
    {
        dim3 grid(NHEADS, BATCH / 2, 1);
        ssm_kernel<<<grid, 256>>>(ssm_in, dt_bias, A_log, Dvec, ssm_p, 0);
    }
    cudaEventRecord(evS0, 0);
    {
        dim3 grid(NHEADS, BATCH / 2, 1);
        ssm_kernel<<<grid, 256>>>(ssm_in, dt_bias, A_log, Dvec, ssm_p, BATCH / 2);
    }

    // ---- stream s1: out_proj half 0 under ssm half 1 ----
    cudaStreamWaitEvent(s1, evS0, 0);
    cudaStreamWaitEvent(s1, evB, 0);
    {
        dim3 grid(D_MODEL / 64, 1, 4);                // rows [0, 128), split-K=4
        gemm_bf16_tc<true><<<grid, 256, GEMM_SMEM, s1>>>(
            yz_hi, yz_lo, op_hi, op_lo, out_p,
            BATCH / 2, D_MODEL, D_SSM, D_SSM / 4);
    }
    cudaEventRecord(evO0, s1);

    // ---- stream 0: out_proj half 1, then join ----
    cudaStreamWaitEvent(0, evB, 0);
    {
        size_t aoff = (size_t)(BATCH / 2) * D_SSM;
        dim3 grid(D_MODEL / 64, 1, 4);                // rows [128, 256)
        gemm_bf16_tc<true><<<grid, 256, GEMM_SMEM>>>(
            yz_hi + aoff, yz_lo + aoff, op_hi, op_lo,
            out_p + (size_t)(BATCH / 2) * D_MODEL,
            BATCH / 2, D_MODEL, D_SSM, D_SSM / 4);
    }
    cudaStreamWaitEvent(0, evO0, 0);
}